// round 1
// baseline (speedup 1.0000x reference)
#include <cuda_runtime.h>
#include <cuda_bf16.h>
#include <math.h>

// Problem constants
constexpr int B   = 2;
constexpr int S   = 2048;
constexpr int DIM = 4096;
constexpr int NH  = 32;
constexpr int NKV = 8;
constexpr int HD  = 128;
constexpr int REP = NH / NKV;   // 4
constexpr int M   = B * S;      // 4096 rows

// Scratch (device globals; no cudaMalloc allowed)
__device__ float g_q[(size_t)B * S * NH * HD];   // 16,777,216
__device__ float g_k[(size_t)B * S * NKV * HD];  //  4,194,304
__device__ float g_v[(size_t)B * S * NKV * HD];
__device__ float g_o[(size_t)B * S * NH * HD];

// ---------------------------------------------------------------------------
// NT SGEMM: C[m][n] = sum_k A[m*K+k] * Bw[n*K+k]
// 64x64 tile, BK=16, 256 threads, 4x4 micro-tile per thread.
// ---------------------------------------------------------------------------
__global__ void sgemm_nt(const float* __restrict__ A, const float* __restrict__ Bw,
                         float* __restrict__ C, int Mr, int Nr, int K) {
    __shared__ float As[16][68];
    __shared__ float Bs[16][68];

    const int bm = blockIdx.y * 64;
    const int bn = blockIdx.x * 64;
    const int tid = threadIdx.x;            // 0..255
    const int tx = tid & 15;
    const int ty = tid >> 4;
    const int lr = tid >> 2;                // 0..63 row within tile
    const int lk = (tid & 3) << 2;          // 0,4,8,12

    const float* Ap = A  + (size_t)(bm + lr) * K + lk;
    const float* Bp = Bw + (size_t)(bn + lr) * K + lk;

    float acc[4][4] = {};

    for (int k0 = 0; k0 < K; k0 += 16) {
        float4 av = *(const float4*)(Ap + k0);
        float4 bv = *(const float4*)(Bp + k0);
        __syncthreads();
        As[lk + 0][lr] = av.x; As[lk + 1][lr] = av.y;
        As[lk + 2][lr] = av.z; As[lk + 3][lr] = av.w;
        Bs[lk + 0][lr] = bv.x; Bs[lk + 1][lr] = bv.y;
        Bs[lk + 2][lr] = bv.z; Bs[lk + 3][lr] = bv.w;
        __syncthreads();
#pragma unroll
        for (int kk = 0; kk < 16; kk++) {
            float4 a4 = *(const float4*)&As[kk][ty << 2];
            float4 b4 = *(const float4*)&Bs[kk][tx << 2];
            float a[4] = {a4.x, a4.y, a4.z, a4.w};
            float b[4] = {b4.x, b4.y, b4.z, b4.w};
#pragma unroll
            for (int i = 0; i < 4; i++)
#pragma unroll
                for (int j = 0; j < 4; j++)
                    acc[i][j] += a[i] * b[j];
        }
    }

#pragma unroll
    for (int i = 0; i < 4; i++) {
        float4 o4 = make_float4(acc[i][0], acc[i][1], acc[i][2], acc[i][3]);
        *(float4*)(C + (size_t)(bm + (ty << 2) + i) * Nr + bn + (tx << 2)) = o4;
    }
}

// ---------------------------------------------------------------------------
// RoPE (interleaved pairs) applied in-place to Q and K.
// ---------------------------------------------------------------------------
__global__ void rope_kernel(float* __restrict__ q, float* __restrict__ k,
                            const float* __restrict__ fc, const float* __restrict__ fs) {
    const int nq = B * S * NH  * (HD / 2);
    const int nk = B * S * NKV * (HD / 2);
    int idx = blockIdx.x * blockDim.x + threadIdx.x;
    float* ptr;
    int s, d;
    if (idx < nq) {
        d = idx & 63;
        int row = idx >> 6;                 // [B,S,NH]
        s = (row / NH) % S;
        ptr = q + (size_t)row * HD + 2 * d;
    } else if (idx < nq + nk) {
        int i2 = idx - nq;
        d = i2 & 63;
        int row = i2 >> 6;                  // [B,S,NKV]
        s = (row / NKV) % S;
        ptr = k + (size_t)row * HD + 2 * d;
    } else {
        return;
    }
    float c  = fc[s * 64 + d];
    float sn = fs[s * 64 + d];
    float xr = ptr[0], xi = ptr[1];
    ptr[0] = xr * c - xi * sn;
    ptr[1] = xr * sn + xi * c;
}

// ---------------------------------------------------------------------------
// Causal flash attention (fp32, online softmax).
// Grid: (B*NH, S/64). 256 threads. 4 threads (a "quad") per Q row.
// smem: Q/K/V tiles with padded stride 132, P with stride 65.
// ---------------------------------------------------------------------------
constexpr int TS  = 132;                   // padded tile row stride (floats)
constexpr int ATTN_SMEM = (3 * 64 * TS + 64 * 65) * 4;   // 118,016 bytes

__global__ void attn_kernel(const float* __restrict__ Q, const float* __restrict__ K,
                            const float* __restrict__ V, float* __restrict__ O) {
    extern __shared__ float sm[];
    float* sQ = sm;
    float* sK = sQ + 64 * TS;
    float* sV = sK + 64 * TS;
    float* sP = sV + 64 * TS;              // 64 x 65

    const int b   = blockIdx.x / NH;
    const int h   = blockIdx.x % NH;
    const int kvh = h / REP;
    const int qt  = blockIdx.y;
    const int tid = threadIdx.x;
    const int r    = tid >> 2;             // q row 0..63
    const int quad = tid & 3;
    const int q0 = qt * 64;
    const float scale = 0.08838834764831845f;   // 1/sqrt(128)

    // Load Q tile
    for (int v = tid; v < 64 * 32; v += 256) {
        int row = v >> 5;
        int c4  = (v & 31) << 2;
        float4 t = *(const float4*)(Q + (((size_t)(b * S + q0 + row)) * NH + h) * HD + c4);
        *(float4*)(sQ + row * TS + c4) = t;
    }

    float mrun = -INFINITY, lrun = 0.f;
    float4 oacc[8];
#pragma unroll
    for (int i = 0; i < 8; i++) oacc[i] = make_float4(0.f, 0.f, 0.f, 0.f);

    for (int kt = 0; kt <= qt; kt++) {
        __syncthreads();
        for (int v = tid; v < 64 * 32; v += 256) {
            int row = v >> 5;
            int c4  = (v & 31) << 2;
            size_t g = (((size_t)(b * S + kt * 64 + row)) * NKV + kvh) * HD + c4;
            *(float4*)(sK + row * TS + c4) = *(const float4*)(K + g);
            *(float4*)(sV + row * TS + c4) = *(const float4*)(V + g);
        }
        __syncthreads();

        // Scores: this thread handles j = quad + 4*jj, jj=0..15
        float acc[16];
#pragma unroll
        for (int jj = 0; jj < 16; jj++) acc[jj] = 0.f;
        for (int d0 = 0; d0 < 128; d0 += 4) {
            float4 qf = *(const float4*)(sQ + r * TS + d0);
#pragma unroll
            for (int jj = 0; jj < 16; jj++) {
                int j = quad + (jj << 2);
                float4 kf = *(const float4*)(sK + j * TS + d0);
                acc[jj] += qf.x * kf.x + qf.y * kf.y + qf.z * kf.z + qf.w * kf.w;
            }
        }

        float tmax = -INFINITY;
#pragma unroll
        for (int jj = 0; jj < 16; jj++) {
            int j = quad + (jj << 2);
            float sc = acc[jj] * scale;
            if (kt * 64 + j > q0 + r) sc = -INFINITY;
            acc[jj] = sc;
            tmax = fmaxf(tmax, sc);
        }
        tmax = fmaxf(tmax, __shfl_xor_sync(0xffffffffu, tmax, 1));
        tmax = fmaxf(tmax, __shfl_xor_sync(0xffffffffu, tmax, 2));

        float mnew  = fmaxf(mrun, tmax);
        float alpha = __expf(mrun - mnew);
        float lsum = 0.f;
#pragma unroll
        for (int jj = 0; jj < 16; jj++) {
            int j = quad + (jj << 2);
            float p = __expf(acc[jj] - mnew);
            lsum += p;
            sP[r * 65 + j] = p;
        }
        lsum += __shfl_xor_sync(0xffffffffu, lsum, 1);
        lsum += __shfl_xor_sync(0xffffffffu, lsum, 2);
        lrun = lrun * alpha + lsum;
        mrun = mnew;
        __syncwarp();   // sP written by quad peers (same warp)

#pragma unroll
        for (int i = 0; i < 8; i++) {
            oacc[i].x *= alpha; oacc[i].y *= alpha;
            oacc[i].z *= alpha; oacc[i].w *= alpha;
        }
        for (int j = 0; j < 64; j++) {
            float p = sP[r * 65 + j];
#pragma unroll
            for (int i = 0; i < 8; i++) {
                float4 vv = *(const float4*)(sV + j * TS + (i << 4) + (quad << 2));
                oacc[i].x += p * vv.x; oacc[i].y += p * vv.y;
                oacc[i].z += p * vv.z; oacc[i].w += p * vv.w;
            }
        }
    }

    const float inv = 1.f / lrun;
    size_t go = (((size_t)(b * S + q0 + r)) * NH + h) * HD + (quad << 2);
#pragma unroll
    for (int i = 0; i < 8; i++) {
        float4 o4 = make_float4(oacc[i].x * inv, oacc[i].y * inv,
                                oacc[i].z * inv, oacc[i].w * inv);
        *(float4*)(O + go + (i << 4)) = o4;
    }
}

// ---------------------------------------------------------------------------
// Launch
// ---------------------------------------------------------------------------
extern "C" void kernel_launch(void* const* d_in, const int* in_sizes, int n_in,
                              void* d_out, int out_size) {
    const float* x  = (const float*)d_in[0];
    const float* wq = (const float*)d_in[1];
    const float* wk = (const float*)d_in[2];
    const float* wv = (const float*)d_in[3];
    const float* wo = (const float*)d_in[4];
    const float* fc = (const float*)d_in[5];
    const float* fs = (const float*)d_in[6];
    // d_in[7] = start_pos (always 0)
    float* out = (float*)d_out;

    float *q, *k, *v, *o;
    cudaGetSymbolAddress((void**)&q, g_q);
    cudaGetSymbolAddress((void**)&k, g_k);
    cudaGetSymbolAddress((void**)&v, g_v);
    cudaGetSymbolAddress((void**)&o, g_o);

    // QKV projections
    sgemm_nt<<<dim3((NH  * HD) / 64, M / 64), 256>>>(x, wq, q, M, NH  * HD, DIM);
    sgemm_nt<<<dim3((NKV * HD) / 64, M / 64), 256>>>(x, wk, k, M, NKV * HD, DIM);
    sgemm_nt<<<dim3((NKV * HD) / 64, M / 64), 256>>>(x, wv, v, M, NKV * HD, DIM);

    // RoPE on Q and K
    int total = B * S * (NH + NKV) * (HD / 2);
    rope_kernel<<<(total + 255) / 256, 256>>>(q, k, fc, fs);

    // Causal GQA flash attention
    cudaFuncSetAttribute(attn_kernel, cudaFuncAttributeMaxDynamicSharedMemorySize, ATTN_SMEM);
    attn_kernel<<<dim3(B * NH, S / 64), 256, ATTN_SMEM>>>(q, k, v, o);

    // Output projection
    sgemm_nt<<<dim3(DIM / 64, M / 64), 256>>>(o, wo, out, M, DIM, DIM);
}

// round 2
// speedup vs baseline: 1.9359x; 1.9359x over previous
#include <cuda_runtime.h>
#include <cuda_bf16.h>
#include <math.h>
#include <stdint.h>

// Problem constants
constexpr int B   = 2;
constexpr int S   = 2048;
constexpr int DIM = 4096;
constexpr int NH  = 32;
constexpr int NKV = 8;
constexpr int HD  = 128;
constexpr int REP = NH / NKV;   // 4
constexpr int M   = B * S;      // 4096 rows

// Scratch (device globals; no cudaMalloc allowed)
__device__ float g_q[(size_t)B * S * NH * HD];
__device__ float g_k[(size_t)B * S * NKV * HD];
__device__ float g_v[(size_t)B * S * NKV * HD];
__device__ float g_o[(size_t)B * S * NH * HD];

// ---------------------------------------------------------------------------
// TF32 tensor-core NT GEMM: C[m][n] = sum_k A[m*K+k] * W[n*K+k]
// 128x128 CTA tile, BK=32, 256 threads (8 warps, 2x4 warp grid, 64x32/warp).
// mma.sync.aligned.m16n8k8.row.col.f32.tf32.tf32.f32
// ---------------------------------------------------------------------------
__device__ __forceinline__ uint32_t f2tf32(float x) {
    uint32_t r;
    asm("cvt.rna.tf32.f32 %0, %1;" : "=r"(r) : "f"(x));
    return r;
}

__device__ __forceinline__ void mma_tf32(float c[4], const uint32_t a[4], const uint32_t b[2]) {
    asm volatile(
        "mma.sync.aligned.m16n8k8.row.col.f32.tf32.tf32.f32 "
        "{%0,%1,%2,%3}, {%4,%5,%6,%7}, {%8,%9}, {%0,%1,%2,%3};"
        : "+f"(c[0]), "+f"(c[1]), "+f"(c[2]), "+f"(c[3])
        : "r"(a[0]), "r"(a[1]), "r"(a[2]), "r"(a[3]), "r"(b[0]), "r"(b[1]));
}

constexpr int GP = 36;   // padded smem stride (uint32)

__global__ void __launch_bounds__(256, 1) gemm_tf32(
    const float* __restrict__ A, const float* __restrict__ W,
    float* __restrict__ C, int Nr, int K)
{
    __shared__ uint32_t As[128][GP];
    __shared__ uint32_t Bs[128][GP];

    const int tid  = threadIdx.x;
    const int lane = tid & 31;
    const int warp = tid >> 5;
    const int wm   = warp & 1;          // 0..1  (m: 64 each)
    const int wn   = warp >> 1;         // 0..3  (n: 32 each)
    const int bm   = blockIdx.y * 128;
    const int bn   = blockIdx.x * 128;

    const int g   = lane >> 2;          // groupID 0..7
    const int tg  = lane & 3;           // thread-in-group

    float acc[4][4][4];
#pragma unroll
    for (int i = 0; i < 4; i++)
#pragma unroll
        for (int j = 0; j < 4; j++)
#pragma unroll
            for (int r = 0; r < 4; r++) acc[i][j][r] = 0.f;

    // Global load mapping: 4 float4 per thread for each tile.
    int ldrow[4], ldc4[4];
#pragma unroll
    for (int i = 0; i < 4; i++) {
        int idx = tid + i * 256;        // 0..1023 float4 slots
        ldrow[i] = idx >> 3;            // 0..127
        ldc4[i]  = (idx & 7) << 2;      // 0,4,..,28
    }

    const int KT = K >> 5;              // K/32 tiles
    float4 pa[4], pb[4];
#pragma unroll
    for (int i = 0; i < 4; i++) {
        pa[i] = *(const float4*)(A + (size_t)(bm + ldrow[i]) * K + ldc4[i]);
        pb[i] = *(const float4*)(W + (size_t)(bn + ldrow[i]) * K + ldc4[i]);
    }

    for (int kt = 0; kt < KT; kt++) {
        __syncthreads();
#pragma unroll
        for (int i = 0; i < 4; i++) {
            As[ldrow[i]][ldc4[i] + 0] = f2tf32(pa[i].x);
            As[ldrow[i]][ldc4[i] + 1] = f2tf32(pa[i].y);
            As[ldrow[i]][ldc4[i] + 2] = f2tf32(pa[i].z);
            As[ldrow[i]][ldc4[i] + 3] = f2tf32(pa[i].w);
            Bs[ldrow[i]][ldc4[i] + 0] = f2tf32(pb[i].x);
            Bs[ldrow[i]][ldc4[i] + 1] = f2tf32(pb[i].y);
            Bs[ldrow[i]][ldc4[i] + 2] = f2tf32(pb[i].z);
            Bs[ldrow[i]][ldc4[i] + 3] = f2tf32(pb[i].w);
        }
        __syncthreads();

        if (kt + 1 < KT) {
            const float* An = A + (size_t)bm * K + (kt + 1) * 32;
            const float* Wn = W + (size_t)bn * K + (kt + 1) * 32;
#pragma unroll
            for (int i = 0; i < 4; i++) {
                pa[i] = *(const float4*)(An + (size_t)ldrow[i] * K + ldc4[i]);
                pb[i] = *(const float4*)(Wn + (size_t)ldrow[i] * K + ldc4[i]);
            }
        }

#pragma unroll
        for (int ks = 0; ks < 4; ks++) {
            const int k0 = ks << 3;
            uint32_t af[4][4], bf[4][2];
#pragma unroll
            for (int mt = 0; mt < 4; mt++) {
                int ra = wm * 64 + mt * 16 + g;
                af[mt][0] = As[ra][k0 + tg];
                af[mt][1] = As[ra + 8][k0 + tg];
                af[mt][2] = As[ra][k0 + tg + 4];
                af[mt][3] = As[ra + 8][k0 + tg + 4];
            }
#pragma unroll
            for (int nt = 0; nt < 4; nt++) {
                int rb = wn * 32 + nt * 8 + g;
                bf[nt][0] = Bs[rb][k0 + tg];
                bf[nt][1] = Bs[rb][k0 + tg + 4];
            }
#pragma unroll
            for (int mt = 0; mt < 4; mt++)
#pragma unroll
                for (int nt = 0; nt < 4; nt++)
                    mma_tf32(acc[mt][nt], af[mt], bf[nt]);
        }
    }

    // Store C
#pragma unroll
    for (int mt = 0; mt < 4; mt++) {
#pragma unroll
        for (int nt = 0; nt < 4; nt++) {
            int row = bm + wm * 64 + mt * 16 + g;
            int col = bn + wn * 32 + nt * 8 + (tg << 1);
            *(float2*)(C + (size_t)row * Nr + col) =
                make_float2(acc[mt][nt][0], acc[mt][nt][1]);
            *(float2*)(C + (size_t)(row + 8) * Nr + col) =
                make_float2(acc[mt][nt][2], acc[mt][nt][3]);
        }
    }
}

// ---------------------------------------------------------------------------
// RoPE (interleaved pairs) applied in-place to Q and K.
// ---------------------------------------------------------------------------
__global__ void rope_kernel(float* __restrict__ q, float* __restrict__ k,
                            const float* __restrict__ fc, const float* __restrict__ fs) {
    const int nq = B * S * NH  * (HD / 2);
    const int nk = B * S * NKV * (HD / 2);
    int idx = blockIdx.x * blockDim.x + threadIdx.x;
    float* ptr;
    int s, d;
    if (idx < nq) {
        d = idx & 63;
        int row = idx >> 6;
        s = (row / NH) % S;
        ptr = q + (size_t)row * HD + 2 * d;
    } else if (idx < nq + nk) {
        int i2 = idx - nq;
        d = i2 & 63;
        int row = i2 >> 6;
        s = (row / NKV) % S;
        ptr = k + (size_t)row * HD + 2 * d;
    } else {
        return;
    }
    float c  = fc[s * 64 + d];
    float sn = fs[s * 64 + d];
    float xr = ptr[0], xi = ptr[1];
    ptr[0] = xr * c - xi * sn;
    ptr[1] = xr * sn + xi * c;
}

// ---------------------------------------------------------------------------
// Causal flash attention (fp32, online softmax). Same as R1.
// ---------------------------------------------------------------------------
constexpr int TS  = 132;
constexpr int ATTN_SMEM = (3 * 64 * TS + 64 * 65) * 4;

__global__ void attn_kernel(const float* __restrict__ Q, const float* __restrict__ K,
                            const float* __restrict__ V, float* __restrict__ O) {
    extern __shared__ float sm[];
    float* sQ = sm;
    float* sK = sQ + 64 * TS;
    float* sV = sK + 64 * TS;
    float* sP = sV + 64 * TS;

    const int b   = blockIdx.x / NH;
    const int h   = blockIdx.x % NH;
    const int kvh = h / REP;
    const int qt  = blockIdx.y;
    const int tid = threadIdx.x;
    const int r    = tid >> 2;
    const int quad = tid & 3;
    const int q0 = qt * 64;
    const float scale = 0.08838834764831845f;

    for (int v = tid; v < 64 * 32; v += 256) {
        int row = v >> 5;
        int c4  = (v & 31) << 2;
        float4 t = *(const float4*)(Q + (((size_t)(b * S + q0 + row)) * NH + h) * HD + c4);
        *(float4*)(sQ + row * TS + c4) = t;
    }

    float mrun = -INFINITY, lrun = 0.f;
    float4 oacc[8];
#pragma unroll
    for (int i = 0; i < 8; i++) oacc[i] = make_float4(0.f, 0.f, 0.f, 0.f);

    for (int kt = 0; kt <= qt; kt++) {
        __syncthreads();
        for (int v = tid; v < 64 * 32; v += 256) {
            int row = v >> 5;
            int c4  = (v & 31) << 2;
            size_t g = (((size_t)(b * S + kt * 64 + row)) * NKV + kvh) * HD + c4;
            *(float4*)(sK + row * TS + c4) = *(const float4*)(K + g);
            *(float4*)(sV + row * TS + c4) = *(const float4*)(V + g);
        }
        __syncthreads();

        float acc[16];
#pragma unroll
        for (int jj = 0; jj < 16; jj++) acc[jj] = 0.f;
        for (int d0 = 0; d0 < 128; d0 += 4) {
            float4 qf = *(const float4*)(sQ + r * TS + d0);
#pragma unroll
            for (int jj = 0; jj < 16; jj++) {
                int j = quad + (jj << 2);
                float4 kf = *(const float4*)(sK + j * TS + d0);
                acc[jj] += qf.x * kf.x + qf.y * kf.y + qf.z * kf.z + qf.w * kf.w;
            }
        }

        float tmax = -INFINITY;
#pragma unroll
        for (int jj = 0; jj < 16; jj++) {
            int j = quad + (jj << 2);
            float sc = acc[jj] * scale;
            if (kt * 64 + j > q0 + r) sc = -INFINITY;
            acc[jj] = sc;
            tmax = fmaxf(tmax, sc);
        }
        tmax = fmaxf(tmax, __shfl_xor_sync(0xffffffffu, tmax, 1));
        tmax = fmaxf(tmax, __shfl_xor_sync(0xffffffffu, tmax, 2));

        float mnew  = fmaxf(mrun, tmax);
        float alpha = __expf(mrun - mnew);
        float lsum = 0.f;
#pragma unroll
        for (int jj = 0; jj < 16; jj++) {
            int j = quad + (jj << 2);
            float p = __expf(acc[jj] - mnew);
            lsum += p;
            sP[r * 65 + j] = p;
        }
        lsum += __shfl_xor_sync(0xffffffffu, lsum, 1);
        lsum += __shfl_xor_sync(0xffffffffu, lsum, 2);
        lrun = lrun * alpha + lsum;
        mrun = mnew;
        __syncwarp();

#pragma unroll
        for (int i = 0; i < 8; i++) {
            oacc[i].x *= alpha; oacc[i].y *= alpha;
            oacc[i].z *= alpha; oacc[i].w *= alpha;
        }
        for (int j = 0; j < 64; j++) {
            float p = sP[r * 65 + j];
#pragma unroll
            for (int i = 0; i < 8; i++) {
                float4 vv = *(const float4*)(sV + j * TS + (i << 4) + (quad << 2));
                oacc[i].x += p * vv.x; oacc[i].y += p * vv.y;
                oacc[i].z += p * vv.z; oacc[i].w += p * vv.w;
            }
        }
    }

    const float inv = 1.f / lrun;
    size_t go = (((size_t)(b * S + q0 + r)) * NH + h) * HD + (quad << 2);
#pragma unroll
    for (int i = 0; i < 8; i++) {
        float4 o4 = make_float4(oacc[i].x * inv, oacc[i].y * inv,
                                oacc[i].z * inv, oacc[i].w * inv);
        *(float4*)(O + go + (i << 4)) = o4;
    }
}

// ---------------------------------------------------------------------------
// Launch
// ---------------------------------------------------------------------------
extern "C" void kernel_launch(void* const* d_in, const int* in_sizes, int n_in,
                              void* d_out, int out_size) {
    const float* x  = (const float*)d_in[0];
    const float* wq = (const float*)d_in[1];
    const float* wk = (const float*)d_in[2];
    const float* wv = (const float*)d_in[3];
    const float* wo = (const float*)d_in[4];
    const float* fc = (const float*)d_in[5];
    const float* fs = (const float*)d_in[6];
    float* out = (float*)d_out;

    float *q, *k, *v, *o;
    cudaGetSymbolAddress((void**)&q, g_q);
    cudaGetSymbolAddress((void**)&k, g_k);
    cudaGetSymbolAddress((void**)&v, g_v);
    cudaGetSymbolAddress((void**)&o, g_o);

    // QKV projections (tf32 tensor cores)
    gemm_tf32<<<dim3((NH  * HD) / 128, M / 128), 256>>>(x, wq, q, NH  * HD, DIM);
    gemm_tf32<<<dim3((NKV * HD) / 128, M / 128), 256>>>(x, wk, k, NKV * HD, DIM);
    gemm_tf32<<<dim3((NKV * HD) / 128, M / 128), 256>>>(x, wv, v, NKV * HD, DIM);

    // RoPE on Q and K
    int total = B * S * (NH + NKV) * (HD / 2);
    rope_kernel<<<(total + 255) / 256, 256>>>(q, k, fc, fs);

    // Causal GQA flash attention
    cudaFuncSetAttribute(attn_kernel, cudaFuncAttributeMaxDynamicSharedMemorySize, ATTN_SMEM);
    attn_kernel<<<dim3(B * NH, S / 64), 256, ATTN_SMEM>>>(q, k, v, o);

    // Output projection
    gemm_tf32<<<dim3(DIM / 128, M / 128), 256>>>(o, wo, out, DIM, DIM);
}

// round 3
// speedup vs baseline: 2.5355x; 1.3098x over previous
#include <cuda_runtime.h>
#include <cuda_bf16.h>
#include <math.h>
#include <stdint.h>

// Problem constants
constexpr int B   = 2;
constexpr int S   = 2048;
constexpr int DIM = 4096;
constexpr int NH  = 32;
constexpr int NKV = 8;
constexpr int HD  = 128;
constexpr int REP = NH / NKV;   // 4
constexpr int M   = B * S;      // 4096 rows

// Scratch (device globals; no cudaMalloc allowed)
__device__ float g_q[(size_t)B * S * NH * HD];
__device__ float g_k[(size_t)B * S * NKV * HD];
__device__ float g_v[(size_t)B * S * NKV * HD];
__device__ float g_o[(size_t)B * S * NH * HD];

// ---------------------------------------------------------------------------
// TF32 tensor-core NT GEMM, cp.async double-buffered.
// C[m][n] = sum_k A[m*K+k] * W[n*K+k]
// 128x128 CTA tile, BK=32, 256 threads (8 warps, 2x4 warp grid, 64x32/warp).
// ---------------------------------------------------------------------------
__device__ __forceinline__ uint32_t f2tf32(float x) {
    uint32_t r;
    asm("cvt.rna.tf32.f32 %0, %1;" : "=r"(r) : "f"(x));
    return r;
}

__device__ __forceinline__ void mma_tf32(float c[4], const uint32_t a[4], const uint32_t b[2]) {
    asm volatile(
        "mma.sync.aligned.m16n8k8.row.col.f32.tf32.tf32.f32 "
        "{%0,%1,%2,%3}, {%4,%5,%6,%7}, {%8,%9}, {%0,%1,%2,%3};"
        : "+f"(c[0]), "+f"(c[1]), "+f"(c[2]), "+f"(c[3])
        : "r"(a[0]), "r"(a[1]), "r"(a[2]), "r"(a[3]), "r"(b[0]), "r"(b[1]));
}

__device__ __forceinline__ void cp_async16(uint32_t saddr, const void* g) {
    asm volatile("cp.async.ca.shared.global [%0], [%1], 16;\n" :: "r"(saddr), "l"(g));
}

constexpr int GP     = 36;                 // padded smem row stride (floats)
constexpr int STAGE  = 128 * GP;           // floats per tile stage
constexpr int GEMM_SMEM = 4 * STAGE * 4;   // 2 stages x (A+B) = 73728 bytes

__global__ void __launch_bounds__(256, 2) gemm_tf32(
    const float* __restrict__ A, const float* __restrict__ W,
    float* __restrict__ C, int Nr, int K)
{
    extern __shared__ float sm[];
    float* sA = sm;                        // [2][128][GP]
    float* sB = sm + 2 * STAGE;            // [2][128][GP]
    const uint32_t sA_b = (uint32_t)__cvta_generic_to_shared(sA);
    const uint32_t sB_b = (uint32_t)__cvta_generic_to_shared(sB);

    const int tid  = threadIdx.x;
    const int lane = tid & 31;
    const int warp = tid >> 5;
    const int wm   = warp & 1;
    const int wn   = warp >> 1;
    const int bm   = blockIdx.y * 128;
    const int bn   = blockIdx.x * 128;
    const int g    = lane >> 2;
    const int tg   = lane & 3;

    float acc[4][4][4];
#pragma unroll
    for (int i = 0; i < 4; i++)
#pragma unroll
        for (int j = 0; j < 4; j++)
#pragma unroll
            for (int r = 0; r < 4; r++) acc[i][j][r] = 0.f;

    // copy mapping: 4 float4 per thread per tile
    int ldrow[4], ldc4[4];
#pragma unroll
    for (int i = 0; i < 4; i++) {
        int idx = tid + i * 256;
        ldrow[i] = idx >> 3;
        ldc4[i]  = (idx & 7) << 2;
    }

    const int KT = K >> 5;

    // prologue: stage 0
#pragma unroll
    for (int i = 0; i < 4; i++) {
        cp_async16(sA_b + (ldrow[i] * GP + ldc4[i]) * 4,
                   A + (size_t)(bm + ldrow[i]) * K + ldc4[i]);
        cp_async16(sB_b + (ldrow[i] * GP + ldc4[i]) * 4,
                   W + (size_t)(bn + ldrow[i]) * K + ldc4[i]);
    }
    asm volatile("cp.async.commit_group;\n");

    for (int kt = 0; kt < KT; kt++) {
        if (kt + 1 < KT) {
            const int st = (kt + 1) & 1;
            const int ko = (kt + 1) << 5;
#pragma unroll
            for (int i = 0; i < 4; i++) {
                cp_async16(sA_b + (st * STAGE + ldrow[i] * GP + ldc4[i]) * 4,
                           A + (size_t)(bm + ldrow[i]) * K + ko + ldc4[i]);
                cp_async16(sB_b + (st * STAGE + ldrow[i] * GP + ldc4[i]) * 4,
                           W + (size_t)(bn + ldrow[i]) * K + ko + ldc4[i]);
            }
        }
        asm volatile("cp.async.commit_group;\n");
        asm volatile("cp.async.wait_group 1;\n");
        __syncthreads();

        const float* As = sA + (kt & 1) * STAGE;
        const float* Bs = sB + (kt & 1) * STAGE;

#pragma unroll
        for (int ks = 0; ks < 4; ks++) {
            const int k0 = ks << 3;
            uint32_t af[4][4], bf[4][2];
#pragma unroll
            for (int mt = 0; mt < 4; mt++) {
                int ra = wm * 64 + mt * 16 + g;
                af[mt][0] = f2tf32(As[ra * GP + k0 + tg]);
                af[mt][1] = f2tf32(As[(ra + 8) * GP + k0 + tg]);
                af[mt][2] = f2tf32(As[ra * GP + k0 + tg + 4]);
                af[mt][3] = f2tf32(As[(ra + 8) * GP + k0 + tg + 4]);
            }
#pragma unroll
            for (int nt = 0; nt < 4; nt++) {
                int rb = wn * 32 + nt * 8 + g;
                bf[nt][0] = f2tf32(Bs[rb * GP + k0 + tg]);
                bf[nt][1] = f2tf32(Bs[rb * GP + k0 + tg + 4]);
            }
#pragma unroll
            for (int mt = 0; mt < 4; mt++)
#pragma unroll
                for (int nt = 0; nt < 4; nt++)
                    mma_tf32(acc[mt][nt], af[mt], bf[nt]);
        }
        __syncthreads();
    }

    // Store C
#pragma unroll
    for (int mt = 0; mt < 4; mt++) {
#pragma unroll
        for (int nt = 0; nt < 4; nt++) {
            int row = bm + wm * 64 + mt * 16 + g;
            int col = bn + wn * 32 + nt * 8 + (tg << 1);
            *(float2*)(C + (size_t)row * Nr + col) =
                make_float2(acc[mt][nt][0], acc[mt][nt][1]);
            *(float2*)(C + (size_t)(row + 8) * Nr + col) =
                make_float2(acc[mt][nt][2], acc[mt][nt][3]);
        }
    }
}

// ---------------------------------------------------------------------------
// RoPE (interleaved pairs) applied in-place to Q and K.
// ---------------------------------------------------------------------------
__global__ void rope_kernel(float* __restrict__ q, float* __restrict__ k,
                            const float* __restrict__ fc, const float* __restrict__ fs) {
    const int nq = B * S * NH  * (HD / 2);
    const int nk = B * S * NKV * (HD / 2);
    int idx = blockIdx.x * blockDim.x + threadIdx.x;
    float* ptr;
    int s, d;
    if (idx < nq) {
        d = idx & 63;
        int row = idx >> 6;
        s = (row / NH) % S;
        ptr = q + (size_t)row * HD + 2 * d;
    } else if (idx < nq + nk) {
        int i2 = idx - nq;
        d = i2 & 63;
        int row = i2 >> 6;
        s = (row / NKV) % S;
        ptr = k + (size_t)row * HD + 2 * d;
    } else {
        return;
    }
    float c  = fc[s * 64 + d];
    float sn = fs[s * 64 + d];
    float xr = ptr[0], xi = ptr[1];
    ptr[0] = xr * c - xi * sn;
    ptr[1] = xr * sn + xi * c;
}

// ---------------------------------------------------------------------------
// Causal flash attention (fp32, online softmax), LDS-optimized:
// each thread owns q-rows {rp, rp+32} and 8 keys (oct), 16-wide HD chunk in PV.
// ---------------------------------------------------------------------------
constexpr int TS  = 132;
constexpr int ATTN_SMEM = (3 * 64 * TS + 64 * 65) * 4;   // 118,016 bytes

__global__ void __launch_bounds__(256, 1)
attn_kernel(const float* __restrict__ Q, const float* __restrict__ K,
            const float* __restrict__ V, float* __restrict__ O) {
    extern __shared__ float sm[];
    float* sQ = sm;
    float* sK = sQ + 64 * TS;
    float* sV = sK + 64 * TS;
    float* sP = sV + 64 * TS;              // 64 x 65

    const int b   = blockIdx.x / NH;
    const int h   = blockIdx.x % NH;
    const int kvh = h / REP;
    const int qt  = blockIdx.y;
    const int tid = threadIdx.x;
    const int rp  = tid >> 3;              // 0..31 (rows rp and rp+32)
    const int oct = tid & 7;               // 0..7
    const int q0  = qt * 64;
    const float scale = 0.08838834764831845f;

    // Load Q tile
    for (int v = tid; v < 64 * 32; v += 256) {
        int row = v >> 5;
        int c4  = (v & 31) << 2;
        float4 t = *(const float4*)(Q + (((size_t)(b * S + q0 + row)) * NH + h) * HD + c4);
        *(float4*)(sQ + row * TS + c4) = t;
    }

    float mrun[2] = {-INFINITY, -INFINITY};
    float lrun[2] = {0.f, 0.f};
    float4 oacc[2][4];
#pragma unroll
    for (int i = 0; i < 2; i++)
#pragma unroll
        for (int c = 0; c < 4; c++) oacc[i][c] = make_float4(0.f, 0.f, 0.f, 0.f);

    for (int kt = 0; kt <= qt; kt++) {
        __syncthreads();
        for (int v = tid; v < 64 * 32; v += 256) {
            int row = v >> 5;
            int c4  = (v & 31) << 2;
            size_t gidx = (((size_t)(b * S + kt * 64 + row)) * NKV + kvh) * HD + c4;
            *(float4*)(sK + row * TS + c4) = *(const float4*)(K + gidx);
            *(float4*)(sV + row * TS + c4) = *(const float4*)(V + gidx);
        }
        __syncthreads();

        // Scores: rows {rp, rp+32} x keys j = oct + 8*jj
        float acc2[2][8];
#pragma unroll
        for (int i = 0; i < 2; i++)
#pragma unroll
            for (int jj = 0; jj < 8; jj++) acc2[i][jj] = 0.f;

        for (int d0 = 0; d0 < 128; d0 += 4) {
            float4 qa = *(const float4*)(sQ + rp * TS + d0);
            float4 qb = *(const float4*)(sQ + (rp + 32) * TS + d0);
#pragma unroll
            for (int jj = 0; jj < 8; jj++) {
                float4 kf = *(const float4*)(sK + (oct + (jj << 3)) * TS + d0);
                acc2[0][jj] += qa.x * kf.x + qa.y * kf.y + qa.z * kf.z + qa.w * kf.w;
                acc2[1][jj] += qb.x * kf.x + qb.y * kf.y + qb.z * kf.z + qb.w * kf.w;
            }
        }

        float alpha[2];
#pragma unroll
        for (int i = 0; i < 2; i++) {
            const int row = rp + 32 * i;
            float tmax = -INFINITY;
#pragma unroll
            for (int jj = 0; jj < 8; jj++) {
                int j = oct + (jj << 3);
                float sc = acc2[i][jj] * scale;
                if (kt * 64 + j > q0 + row) sc = -INFINITY;
                acc2[i][jj] = sc;
                tmax = fmaxf(tmax, sc);
            }
            tmax = fmaxf(tmax, __shfl_xor_sync(0xffffffffu, tmax, 1));
            tmax = fmaxf(tmax, __shfl_xor_sync(0xffffffffu, tmax, 2));
            tmax = fmaxf(tmax, __shfl_xor_sync(0xffffffffu, tmax, 4));

            float mnew = fmaxf(mrun[i], tmax);
            alpha[i] = __expf(mrun[i] - mnew);
            float lsum = 0.f;
#pragma unroll
            for (int jj = 0; jj < 8; jj++) {
                int j = oct + (jj << 3);
                float p = __expf(acc2[i][jj] - mnew);
                lsum += p;
                sP[row * 65 + j] = p;
            }
            lsum += __shfl_xor_sync(0xffffffffu, lsum, 1);
            lsum += __shfl_xor_sync(0xffffffffu, lsum, 2);
            lsum += __shfl_xor_sync(0xffffffffu, lsum, 4);
            lrun[i] = lrun[i] * alpha[i] + lsum;
            mrun[i] = mnew;
        }
        __syncwarp();   // sP for rows rp/rp+32 written by the 8 lanes sharing rp (same warp)

#pragma unroll
        for (int i = 0; i < 2; i++)
#pragma unroll
            for (int c = 0; c < 4; c++) {
                oacc[i][c].x *= alpha[i]; oacc[i][c].y *= alpha[i];
                oacc[i][c].z *= alpha[i]; oacc[i][c].w *= alpha[i];
            }

        // PV: staggered j to avoid V bank conflicts
        for (int jj = 0; jj < 64; jj++) {
            int j = (jj + oct) & 63;
            float p0 = sP[rp * 65 + j];
            float p1 = sP[(rp + 32) * 65 + j];
            const float* vb = sV + j * TS + (oct << 4);
#pragma unroll
            for (int c = 0; c < 4; c++) {
                float4 vv = *(const float4*)(vb + (c << 2));
                oacc[0][c].x += p0 * vv.x; oacc[0][c].y += p0 * vv.y;
                oacc[0][c].z += p0 * vv.z; oacc[0][c].w += p0 * vv.w;
                oacc[1][c].x += p1 * vv.x; oacc[1][c].y += p1 * vv.y;
                oacc[1][c].z += p1 * vv.z; oacc[1][c].w += p1 * vv.w;
            }
        }
    }

#pragma unroll
    for (int i = 0; i < 2; i++) {
        const int row = rp + 32 * i;
        const float inv = 1.f / lrun[i];
        size_t go = (((size_t)(b * S + q0 + row)) * NH + h) * HD + (oct << 4);
#pragma unroll
        for (int c = 0; c < 4; c++) {
            float4 o4 = make_float4(oacc[i][c].x * inv, oacc[i][c].y * inv,
                                    oacc[i][c].z * inv, oacc[i][c].w * inv);
            *(float4*)(O + go + (c << 2)) = o4;
        }
    }
}

// ---------------------------------------------------------------------------
// Launch
// ---------------------------------------------------------------------------
extern "C" void kernel_launch(void* const* d_in, const int* in_sizes, int n_in,
                              void* d_out, int out_size) {
    const float* x  = (const float*)d_in[0];
    const float* wq = (const float*)d_in[1];
    const float* wk = (const float*)d_in[2];
    const float* wv = (const float*)d_in[3];
    const float* wo = (const float*)d_in[4];
    const float* fc = (const float*)d_in[5];
    const float* fs = (const float*)d_in[6];
    float* out = (float*)d_out;

    float *q, *k, *v, *o;
    cudaGetSymbolAddress((void**)&q, g_q);
    cudaGetSymbolAddress((void**)&k, g_k);
    cudaGetSymbolAddress((void**)&v, g_v);
    cudaGetSymbolAddress((void**)&o, g_o);

    cudaFuncSetAttribute(gemm_tf32, cudaFuncAttributeMaxDynamicSharedMemorySize, GEMM_SMEM);
    cudaFuncSetAttribute(attn_kernel, cudaFuncAttributeMaxDynamicSharedMemorySize, ATTN_SMEM);

    // QKV projections (tf32 tensor cores, cp.async pipeline)
    gemm_tf32<<<dim3((NH  * HD) / 128, M / 128), 256, GEMM_SMEM>>>(x, wq, q, NH  * HD, DIM);
    gemm_tf32<<<dim3((NKV * HD) / 128, M / 128), 256, GEMM_SMEM>>>(x, wk, k, NKV * HD, DIM);
    gemm_tf32<<<dim3((NKV * HD) / 128, M / 128), 256, GEMM_SMEM>>>(x, wv, v, NKV * HD, DIM);

    // RoPE on Q and K
    int total = B * S * (NH + NKV) * (HD / 2);
    rope_kernel<<<(total + 255) / 256, 256>>>(q, k, fc, fs);

    // Causal GQA flash attention
    attn_kernel<<<dim3(B * NH, S / 64), 256, ATTN_SMEM>>>(q, k, v, o);

    // Output projection
    gemm_tf32<<<dim3(DIM / 128, M / 128), 256, GEMM_SMEM>>>(o, wo, out, DIM, DIM);
}

// round 4
// speedup vs baseline: 4.5782x; 1.8056x over previous
#include <cuda_runtime.h>
#include <cuda_bf16.h>
#include <math.h>
#include <stdint.h>

// Problem constants
constexpr int B   = 2;
constexpr int S   = 2048;
constexpr int DIM = 4096;
constexpr int NH  = 32;
constexpr int NKV = 8;
constexpr int HD  = 128;
constexpr int REP = NH / NKV;   // 4
constexpr int M   = B * S;      // 4096 rows

// Scratch (device globals; no cudaMalloc allowed)
__device__ float    g_q[(size_t)B * S * NH * HD];
__device__ float    g_k[(size_t)B * S * NKV * HD];
__device__ float    g_v[(size_t)B * S * NKV * HD];
__device__ float    g_o[(size_t)B * S * NH * HD];
__device__ uint32_t g_qp[(size_t)B * NH * S * HD];    // packed split, [b][h][s][d]
__device__ uint32_t g_kp[(size_t)B * NKV * S * HD];   // packed split, [b][kvh][s][d]
__device__ uint32_t g_vpt[(size_t)B * NKV * HD * S];  // packed split, [b][kvh][d][s]

// ---------------------------------------------------------------------------
// Common helpers
// ---------------------------------------------------------------------------
__device__ __forceinline__ uint32_t f2tf32(float x) {
    uint32_t r;
    asm("cvt.rna.tf32.f32 %0, %1;" : "=r"(r) : "f"(x));
    return r;
}

__device__ __forceinline__ void mma_tf32(float c[4], const uint32_t a[4], const uint32_t b[2]) {
    asm volatile(
        "mma.sync.aligned.m16n8k8.row.col.f32.tf32.tf32.f32 "
        "{%0,%1,%2,%3}, {%4,%5,%6,%7}, {%8,%9}, {%0,%1,%2,%3};"
        : "+f"(c[0]), "+f"(c[1]), "+f"(c[2]), "+f"(c[3])
        : "r"(a[0]), "r"(a[1]), "r"(a[2]), "r"(a[3]), "r"(b[0]), "r"(b[1]));
}

__device__ __forceinline__ void mma_bf16(float c[4], const uint32_t a[4], const uint32_t b[2]) {
    asm volatile(
        "mma.sync.aligned.m16n8k16.row.col.f32.bf16.bf16.f32 "
        "{%0,%1,%2,%3}, {%4,%5,%6,%7}, {%8,%9}, {%0,%1,%2,%3};"
        : "+f"(c[0]), "+f"(c[1]), "+f"(c[2]), "+f"(c[3])
        : "r"(a[0]), "r"(a[1]), "r"(a[2]), "r"(a[3]), "r"(b[0]), "r"(b[1]));
}

__device__ __forceinline__ void cp_async16(uint32_t saddr, const void* g) {
    asm volatile("cp.async.ca.shared.global [%0], [%1], 16;\n" :: "r"(saddr), "l"(g));
}

// packed element: low16 = bf16(hi part), high16 = bf16(residual)
__device__ __forceinline__ uint32_t packsplit(float x) {
    __nv_bfloat16 hb = __float2bfloat16(x);
    float l = x - __bfloat162float(hb);
    __nv_bfloat16 lb = __float2bfloat16(l);
    return ((uint32_t)__bfloat16_as_ushort(lb) << 16) | (uint32_t)__bfloat16_as_ushort(hb);
}

// load two adjacent packed elements -> (hi-pair, lo-pair) bf16x2 regs (k-even in low half)
__device__ __forceinline__ void ldpair(const uint32_t* p, uint32_t& hi, uint32_t& lo) {
    uint2 e = *(const uint2*)p;
    hi = __byte_perm(e.x, e.y, 0x5410);
    lo = __byte_perm(e.x, e.y, 0x7632);
}

// split two fp32 into packed (hi-pair, lo-pair); x0 goes into low half
__device__ __forceinline__ void split2(float x0, float x1, uint32_t& hi, uint32_t& lo) {
    uint32_t h;
    asm("cvt.rn.bf16x2.f32 %0, %1, %2;" : "=r"(h) : "f"(x1), "f"(x0));
    float h0 = __uint_as_float(h << 16);
    float h1 = __uint_as_float(h & 0xffff0000u);
    float l0 = x0 - h0, l1 = x1 - h1;
    asm("cvt.rn.bf16x2.f32 %0, %1, %2;" : "=r"(lo) : "f"(l1), "f"(l0));
    hi = h;
}

// ---------------------------------------------------------------------------
// TF32 tensor-core NT GEMM, cp.async double-buffered (unchanged from R3).
// ---------------------------------------------------------------------------
constexpr int GP     = 36;
constexpr int STAGE  = 128 * GP;
constexpr int GEMM_SMEM = 4 * STAGE * 4;   // 73728 bytes

__global__ void __launch_bounds__(256, 2) gemm_tf32(
    const float* __restrict__ A, const float* __restrict__ W,
    float* __restrict__ C, int Nr, int K)
{
    extern __shared__ float sm[];
    float* sA = sm;
    float* sB = sm + 2 * STAGE;
    const uint32_t sA_b = (uint32_t)__cvta_generic_to_shared(sA);
    const uint32_t sB_b = (uint32_t)__cvta_generic_to_shared(sB);

    const int tid  = threadIdx.x;
    const int lane = tid & 31;
    const int warp = tid >> 5;
    const int wm   = warp & 1;
    const int wn   = warp >> 1;
    const int bm   = blockIdx.y * 128;
    const int bn   = blockIdx.x * 128;
    const int g    = lane >> 2;
    const int tg   = lane & 3;

    float acc[4][4][4];
#pragma unroll
    for (int i = 0; i < 4; i++)
#pragma unroll
        for (int j = 0; j < 4; j++)
#pragma unroll
            for (int r = 0; r < 4; r++) acc[i][j][r] = 0.f;

    int ldrow[4], ldc4[4];
#pragma unroll
    for (int i = 0; i < 4; i++) {
        int idx = tid + i * 256;
        ldrow[i] = idx >> 3;
        ldc4[i]  = (idx & 7) << 2;
    }

    const int KT = K >> 5;

#pragma unroll
    for (int i = 0; i < 4; i++) {
        cp_async16(sA_b + (ldrow[i] * GP + ldc4[i]) * 4,
                   A + (size_t)(bm + ldrow[i]) * K + ldc4[i]);
        cp_async16(sB_b + (ldrow[i] * GP + ldc4[i]) * 4,
                   W + (size_t)(bn + ldrow[i]) * K + ldc4[i]);
    }
    asm volatile("cp.async.commit_group;\n");

    for (int kt = 0; kt < KT; kt++) {
        if (kt + 1 < KT) {
            const int st = (kt + 1) & 1;
            const int ko = (kt + 1) << 5;
#pragma unroll
            for (int i = 0; i < 4; i++) {
                cp_async16(sA_b + (st * STAGE + ldrow[i] * GP + ldc4[i]) * 4,
                           A + (size_t)(bm + ldrow[i]) * K + ko + ldc4[i]);
                cp_async16(sB_b + (st * STAGE + ldrow[i] * GP + ldc4[i]) * 4,
                           W + (size_t)(bn + ldrow[i]) * K + ko + ldc4[i]);
            }
        }
        asm volatile("cp.async.commit_group;\n");
        asm volatile("cp.async.wait_group 1;\n");
        __syncthreads();

        const float* As = sA + (kt & 1) * STAGE;
        const float* Bs = sB + (kt & 1) * STAGE;

#pragma unroll
        for (int ks = 0; ks < 4; ks++) {
            const int k0 = ks << 3;
            uint32_t af[4][4], bf[4][2];
#pragma unroll
            for (int mt = 0; mt < 4; mt++) {
                int ra = wm * 64 + mt * 16 + g;
                af[mt][0] = f2tf32(As[ra * GP + k0 + tg]);
                af[mt][1] = f2tf32(As[(ra + 8) * GP + k0 + tg]);
                af[mt][2] = f2tf32(As[ra * GP + k0 + tg + 4]);
                af[mt][3] = f2tf32(As[(ra + 8) * GP + k0 + tg + 4]);
            }
#pragma unroll
            for (int nt = 0; nt < 4; nt++) {
                int rb = wn * 32 + nt * 8 + g;
                bf[nt][0] = f2tf32(Bs[rb * GP + k0 + tg]);
                bf[nt][1] = f2tf32(Bs[rb * GP + k0 + tg + 4]);
            }
#pragma unroll
            for (int mt = 0; mt < 4; mt++)
#pragma unroll
                for (int nt = 0; nt < 4; nt++)
                    mma_tf32(acc[mt][nt], af[mt], bf[nt]);
        }
        __syncthreads();
    }

#pragma unroll
    for (int mt = 0; mt < 4; mt++) {
#pragma unroll
        for (int nt = 0; nt < 4; nt++) {
            int row = bm + wm * 64 + mt * 16 + g;
            int col = bn + wn * 32 + nt * 8 + (tg << 1);
            *(float2*)(C + (size_t)row * Nr + col) =
                make_float2(acc[mt][nt][0], acc[mt][nt][1]);
            *(float2*)(C + (size_t)(row + 8) * Nr + col) =
                make_float2(acc[mt][nt][2], acc[mt][nt][3]);
        }
    }
}

// ---------------------------------------------------------------------------
// Fused RoPE + bf16-split pack + layout transform.
// q -> qp [b][h][s][d] ; k -> kp [b][kvh][s][d] ; v -> vpt [b][kvh][d][s]
// ---------------------------------------------------------------------------
__global__ void ropepack(const float* __restrict__ q, const float* __restrict__ k,
                         const float* __restrict__ v,
                         const float* __restrict__ fc, const float* __restrict__ fs,
                         uint32_t* __restrict__ qp, uint32_t* __restrict__ kp,
                         uint32_t* __restrict__ vpt) {
    const int NQ = B * NH  * S * 64;   // q pairs
    const int NK = B * NKV * S * 64;   // k pairs
    int idx = blockIdx.x * blockDim.x + threadIdx.x;

    if (idx < NQ) {
        int d = idx & 63;
        int s = (idx >> 6) & (S - 1);
        int h = (idx >> 17) & 31;
        int b = idx >> 22;
        const float* src = q + ((size_t)(b * S + s) * NH + h) * HD + 2 * d;
        float xr = src[0], xi = src[1];
        float c = fc[s * 64 + d], sn = fs[s * 64 + d];
        float orr = xr * c - xi * sn;
        float oii = xr * sn + xi * c;
        *(uint2*)(qp + 2 * (size_t)idx) = make_uint2(packsplit(orr), packsplit(oii));
    } else if (idx < NQ + NK) {
        int i2 = idx - NQ;
        int d = i2 & 63;
        int s = (i2 >> 6) & (S - 1);
        int kvh = (i2 >> 17) & 7;
        int b = i2 >> 20;
        const float* src = k + ((size_t)(b * S + s) * NKV + kvh) * HD + 2 * d;
        float xr = src[0], xi = src[1];
        float c = fc[s * 64 + d], sn = fs[s * 64 + d];
        float orr = xr * c - xi * sn;
        float oii = xr * sn + xi * c;
        *(uint2*)(kp + 2 * (size_t)i2) = make_uint2(packsplit(orr), packsplit(oii));
    } else {
        int i3 = idx - NQ - NK;           // [b][kvh][d][s]
        int s = i3 & (S - 1);
        int d = (i3 >> 11) & 127;
        int kvh = (i3 >> 18) & 7;
        int b = i3 >> 21;
        float x = v[((size_t)(b * S + s) * NKV + kvh) * HD + d];
        vpt[i3] = packsplit(x);
    }
}

// ---------------------------------------------------------------------------
// Flash attention v2 with bf16x2-split mma.sync (numerically ~fp32).
// CTA: 128 q rows x 64-key kv tiles, 256 threads, warp = m16 x n64(full).
// smem: Q[128][136], K[2][64][136], V[2][128][72] (packed uint32).
// ---------------------------------------------------------------------------
constexpr int QSTR = 136, KSTR = 136, VSTR = 72;
constexpr int SQ_OFF = 0;
constexpr int SK_OFF = 128 * QSTR;             // 17408
constexpr int SV_OFF = SK_OFF + 2 * 64 * KSTR; // 34816
constexpr int ATTN_SMEM = (SV_OFF + 2 * 128 * VSTR) * 4;   // 212992 bytes

__global__ void __launch_bounds__(256, 1)
attn_mma(const uint32_t* __restrict__ qp, const uint32_t* __restrict__ kp,
         const uint32_t* __restrict__ vpt, float* __restrict__ O) {
    extern __shared__ uint32_t smw[];
    const uint32_t smb = (uint32_t)__cvta_generic_to_shared(smw);

    const int bh  = blockIdx.x;
    const int b   = bh >> 5;
    const int h   = bh & 31;
    const int kvh = h >> 2;
    const int qt  = blockIdx.y;
    const int qbase = qt * 128;
    const int tid = threadIdx.x;
    const int lane = tid & 31;
    const int w = tid >> 5;
    const int g = lane >> 2;
    const int tg = lane & 3;
    const float scale = 0.08838834764831845f;

    const uint32_t* qsrc = qp + ((size_t)(b * NH + h) * S + qbase) * HD;
    const uint32_t* ksrc = kp + (size_t)(b * NKV + kvh) * S * HD;
    const uint32_t* vsrc = vpt + (size_t)(b * NKV + kvh) * HD * S;

    // Q tile: 128 rows x 32 chunks
    for (int i = tid; i < 4096; i += 256) {
        int r = i >> 5, c = (i & 31) << 2;
        cp_async16(smb + (SQ_OFF + r * QSTR + c) * 4, qsrc + r * 128 + c);
    }
    // KV tile 0
    {
        for (int i = tid; i < 2048; i += 256) {
            int r = i >> 5, c = (i & 31) << 2;
            cp_async16(smb + (SK_OFF + r * KSTR + c) * 4, ksrc + r * 128 + c);
        }
        for (int i = tid; i < 2048; i += 256) {
            int d = i >> 4, c = (i & 15) << 2;
            cp_async16(smb + (SV_OFF + d * VSTR + c) * 4, vsrc + (size_t)d * S + c);
        }
    }
    asm volatile("cp.async.commit_group;\n");

    float oacc[16][4];
#pragma unroll
    for (int nt = 0; nt < 16; nt++)
#pragma unroll
        for (int j = 0; j < 4; j++) oacc[nt][j] = 0.f;
    float mrun[2] = {-INFINITY, -INFINITY};
    float lrun[2] = {0.f, 0.f};

    const int nkv = 2 * qt + 2;
    const int rowbase = qbase + w * 16;

    for (int kt = 0; kt < nkv; kt++) {
        __syncthreads();
        if (kt + 1 < nkv) {
            const int st = (kt + 1) & 1;
            const uint32_t* ks = ksrc + (size_t)(kt + 1) * 64 * 128;
            for (int i = tid; i < 2048; i += 256) {
                int r = i >> 5, c = (i & 31) << 2;
                cp_async16(smb + (SK_OFF + st * 64 * KSTR + r * KSTR + c) * 4,
                           ks + r * 128 + c);
            }
            const uint32_t* vs = vsrc + (kt + 1) * 64;
            for (int i = tid; i < 2048; i += 256) {
                int d = i >> 4, c = (i & 15) << 2;
                cp_async16(smb + (SV_OFF + st * 128 * VSTR + d * VSTR + c) * 4,
                           vs + (size_t)d * S + c);
            }
        }
        asm volatile("cp.async.commit_group;\n");
        asm volatile("cp.async.wait_group 1;\n");
        __syncthreads();

        const bool active = (kt * 64 <= rowbase + 15);
        if (!active) continue;

        const uint32_t* K0 = smw + SK_OFF + (kt & 1) * 64 * KSTR;
        const uint32_t* V0 = smw + SV_OFF + (kt & 1) * 128 * VSTR;
        const uint32_t* Q0 = smw + SQ_OFF;

        // ---- QK^T ----
        float accS[8][4];
#pragma unroll
        for (int nt = 0; nt < 8; nt++)
#pragma unroll
            for (int j = 0; j < 4; j++) accS[nt][j] = 0.f;

#pragma unroll
        for (int s = 0; s < 8; s++) {
            const int d0 = 16 * s + 2 * tg;
            uint32_t ah[4], al[4];
            ldpair(Q0 + (w * 16 + g) * QSTR + d0,     ah[0], al[0]);
            ldpair(Q0 + (w * 16 + g + 8) * QSTR + d0, ah[1], al[1]);
            ldpair(Q0 + (w * 16 + g) * QSTR + d0 + 8, ah[2], al[2]);
            ldpair(Q0 + (w * 16 + g + 8) * QSTR + d0 + 8, ah[3], al[3]);
#pragma unroll
            for (int nt = 0; nt < 8; nt++) {
                uint32_t bh2[2], bl2[2];
                ldpair(K0 + (nt * 8 + g) * KSTR + d0,     bh2[0], bl2[0]);
                ldpair(K0 + (nt * 8 + g) * KSTR + d0 + 8, bh2[1], bl2[1]);
                mma_bf16(accS[nt], ah, bh2);
                mma_bf16(accS[nt], ah, bl2);
                mma_bf16(accS[nt], al, bh2);
            }
        }

        // ---- softmax (online) ----
        const bool needM = (kt * 64 + 63 > rowbase);
        float mt[2] = {-INFINITY, -INFINITY};
#pragma unroll
        for (int nt = 0; nt < 8; nt++) {
#pragma unroll
            for (int j = 0; j < 4; j++) {
                float sc = accS[nt][j] * scale;
                if (needM) {
                    int col = kt * 64 + nt * 8 + 2 * tg + (j & 1);
                    int row = rowbase + g + ((j >> 1) << 3);
                    if (col > row) sc = -1e30f;
                }
                accS[nt][j] = sc;
                mt[j >> 1] = fmaxf(mt[j >> 1], sc);
            }
        }
#pragma unroll
        for (int i = 0; i < 2; i++) {
            mt[i] = fmaxf(mt[i], __shfl_xor_sync(0xffffffffu, mt[i], 1));
            mt[i] = fmaxf(mt[i], __shfl_xor_sync(0xffffffffu, mt[i], 2));
        }
        float alpha[2], ls[2] = {0.f, 0.f};
#pragma unroll
        for (int i = 0; i < 2; i++) {
            float mnew = fmaxf(mrun[i], mt[i]);
            alpha[i] = __expf(mrun[i] - mnew);
            mrun[i] = mnew;
        }
#pragma unroll
        for (int nt = 0; nt < 8; nt++) {
#pragma unroll
            for (int j = 0; j < 4; j++) {
                float p = __expf(accS[nt][j] - mrun[j >> 1]);
                accS[nt][j] = p;
                ls[j >> 1] += p;
            }
        }
#pragma unroll
        for (int i = 0; i < 2; i++) {
            ls[i] += __shfl_xor_sync(0xffffffffu, ls[i], 1);
            ls[i] += __shfl_xor_sync(0xffffffffu, ls[i], 2);
            lrun[i] = lrun[i] * alpha[i] + ls[i];
        }
#pragma unroll
        for (int nt = 0; nt < 16; nt++) {
            oacc[nt][0] *= alpha[0]; oacc[nt][1] *= alpha[0];
            oacc[nt][2] *= alpha[1]; oacc[nt][3] *= alpha[1];
        }

        // ---- P @ V ----
#pragma unroll
        for (int s = 0; s < 4; s++) {
            uint32_t ph[4], pl[4];
            split2(accS[2 * s][0],     accS[2 * s][1],     ph[0], pl[0]);
            split2(accS[2 * s][2],     accS[2 * s][3],     ph[1], pl[1]);
            split2(accS[2 * s + 1][0], accS[2 * s + 1][1], ph[2], pl[2]);
            split2(accS[2 * s + 1][2], accS[2 * s + 1][3], ph[3], pl[3]);
            const int k0 = 16 * s + 2 * tg;
#pragma unroll
            for (int nt = 0; nt < 16; nt++) {
                uint32_t bh2[2], bl2[2];
                ldpair(V0 + (nt * 8 + g) * VSTR + k0,     bh2[0], bl2[0]);
                ldpair(V0 + (nt * 8 + g) * VSTR + k0 + 8, bh2[1], bl2[1]);
                mma_bf16(oacc[nt], ph, bh2);
                mma_bf16(oacc[nt], ph, bl2);
                mma_bf16(oacc[nt], pl, bh2);
            }
        }
    }

    // ---- write output [b][s][h][d] ----
    const float i0 = 1.f / lrun[0];
    const float i1 = 1.f / lrun[1];
    const int row0 = rowbase + g;
    float* o0 = O + ((size_t)(b * S + row0) * NH + h) * HD;
    float* o1 = O + ((size_t)(b * S + row0 + 8) * NH + h) * HD;
#pragma unroll
    for (int nt = 0; nt < 16; nt++) {
        int col = nt * 8 + 2 * tg;
        *(float2*)(o0 + col) = make_float2(oacc[nt][0] * i0, oacc[nt][1] * i0);
        *(float2*)(o1 + col) = make_float2(oacc[nt][2] * i1, oacc[nt][3] * i1);
    }
}

// ---------------------------------------------------------------------------
// Launch
// ---------------------------------------------------------------------------
extern "C" void kernel_launch(void* const* d_in, const int* in_sizes, int n_in,
                              void* d_out, int out_size) {
    const float* x  = (const float*)d_in[0];
    const float* wq = (const float*)d_in[1];
    const float* wk = (const float*)d_in[2];
    const float* wv = (const float*)d_in[3];
    const float* wo = (const float*)d_in[4];
    const float* fc = (const float*)d_in[5];
    const float* fs = (const float*)d_in[6];
    float* out = (float*)d_out;

    float *q, *k, *v, *o;
    uint32_t *qpp, *kpp, *vptp;
    cudaGetSymbolAddress((void**)&q, g_q);
    cudaGetSymbolAddress((void**)&k, g_k);
    cudaGetSymbolAddress((void**)&v, g_v);
    cudaGetSymbolAddress((void**)&o, g_o);
    cudaGetSymbolAddress((void**)&qpp, g_qp);
    cudaGetSymbolAddress((void**)&kpp, g_kp);
    cudaGetSymbolAddress((void**)&vptp, g_vpt);

    cudaFuncSetAttribute(gemm_tf32, cudaFuncAttributeMaxDynamicSharedMemorySize, GEMM_SMEM);
    cudaFuncSetAttribute(attn_mma, cudaFuncAttributeMaxDynamicSharedMemorySize, ATTN_SMEM);

    // QKV projections (tf32 tensor cores, cp.async pipeline)
    gemm_tf32<<<dim3((NH  * HD) / 128, M / 128), 256, GEMM_SMEM>>>(x, wq, q, NH  * HD, DIM);
    gemm_tf32<<<dim3((NKV * HD) / 128, M / 128), 256, GEMM_SMEM>>>(x, wk, k, NKV * HD, DIM);
    gemm_tf32<<<dim3((NKV * HD) / 128, M / 128), 256, GEMM_SMEM>>>(x, wv, v, NKV * HD, DIM);

    // RoPE + split-pack + layout transform
    int total = B * NH * S * 64 + B * NKV * S * 64 + B * NKV * HD * S;
    ropepack<<<total / 256, 256>>>(q, k, v, fc, fs, qpp, kpp, vptp);

    // Tensor-core causal GQA flash attention
    attn_mma<<<dim3(B * NH, S / 128), 256, ATTN_SMEM>>>(qpp, kpp, vptp, o);

    // Output projection
    gemm_tf32<<<dim3(DIM / 128, M / 128), 256, GEMM_SMEM>>>(o, wo, out, DIM, DIM);
}

// round 6
// speedup vs baseline: 4.7640x; 1.0406x over previous
#include <cuda_runtime.h>
#include <cuda_bf16.h>
#include <math.h>
#include <stdint.h>

// Problem constants
constexpr int B   = 2;
constexpr int S   = 2048;
constexpr int DIM = 4096;
constexpr int NH  = 32;
constexpr int NKV = 8;
constexpr int HD  = 128;
constexpr int REP = NH / NKV;   // 4
constexpr int M   = B * S;      // 4096 rows

// Scratch (device globals; no cudaMalloc allowed)
__device__ float    g_q[(size_t)B * S * NH * HD];
__device__ float    g_k[(size_t)B * S * NKV * HD];
__device__ float    g_v[(size_t)B * S * NKV * HD];
__device__ float    g_o[(size_t)B * S * NH * HD];
__device__ uint32_t g_qp[(size_t)B * NH * S * HD];    // packed split, [b][h][s][d]
__device__ uint32_t g_kp[(size_t)B * NKV * S * HD];   // packed split, [b][kvh][s][d]
__device__ uint32_t g_vpt[(size_t)B * NKV * HD * S];  // packed split, [b][kvh][d][s]

// ---------------------------------------------------------------------------
// Helpers
// ---------------------------------------------------------------------------
__device__ __forceinline__ uint32_t f2tf32(float x) {
    uint32_t r;
    asm("cvt.rna.tf32.f32 %0, %1;" : "=r"(r) : "f"(x));
    return r;
}

__device__ __forceinline__ void mma_tf32(float c[4], const uint32_t a[4], const uint32_t b[2]) {
    asm volatile(
        "mma.sync.aligned.m16n8k8.row.col.f32.tf32.tf32.f32 "
        "{%0,%1,%2,%3}, {%4,%5,%6,%7}, {%8,%9}, {%0,%1,%2,%3};"
        : "+f"(c[0]), "+f"(c[1]), "+f"(c[2]), "+f"(c[3])
        : "r"(a[0]), "r"(a[1]), "r"(a[2]), "r"(a[3]), "r"(b[0]), "r"(b[1]));
}

__device__ __forceinline__ void mma_bf16(float c[4], const uint32_t a[4], const uint32_t b[2]) {
    asm volatile(
        "mma.sync.aligned.m16n8k16.row.col.f32.bf16.bf16.f32 "
        "{%0,%1,%2,%3}, {%4,%5,%6,%7}, {%8,%9}, {%0,%1,%2,%3};"
        : "+f"(c[0]), "+f"(c[1]), "+f"(c[2]), "+f"(c[3])
        : "r"(a[0]), "r"(a[1]), "r"(a[2]), "r"(a[3]), "r"(b[0]), "r"(b[1]));
}

__device__ __forceinline__ void cp_async16(uint32_t saddr, const void* g) {
    asm volatile("cp.async.ca.shared.global [%0], [%1], 16;\n" :: "r"(saddr), "l"(g));
}

__device__ __forceinline__ void ldm_x4(uint32_t& r0, uint32_t& r1, uint32_t& r2, uint32_t& r3,
                                       uint32_t addr) {
    asm volatile("ldmatrix.sync.aligned.m8n8.x4.shared.b16 {%0,%1,%2,%3}, [%4];"
                 : "=r"(r0), "=r"(r1), "=r"(r2), "=r"(r3) : "r"(addr));
}

__device__ __forceinline__ uint32_t packsplit(float x) {
    __nv_bfloat16 hb = __float2bfloat16(x);
    float l = x - __bfloat162float(hb);
    __nv_bfloat16 lb = __float2bfloat16(l);
    return ((uint32_t)__bfloat16_as_ushort(lb) << 16) | (uint32_t)__bfloat16_as_ushort(hb);
}

__device__ __forceinline__ void ldpair(const uint32_t* p, uint32_t& hi, uint32_t& lo) {
    uint2 e = *(const uint2*)p;
    hi = __byte_perm(e.x, e.y, 0x5410);
    lo = __byte_perm(e.x, e.y, 0x7632);
}

__device__ __forceinline__ void split2(float x0, float x1, uint32_t& hi, uint32_t& lo) {
    uint32_t h;
    asm("cvt.rn.bf16x2.f32 %0, %1, %2;" : "=r"(h) : "f"(x1), "f"(x0));
    float h0 = __uint_as_float(h << 16);
    float h1 = __uint_as_float(h & 0xffff0000u);
    float l0 = x0 - h0, l1 = x1 - h1;
    asm("cvt.rn.bf16x2.f32 %0, %1, %2;" : "=r"(lo) : "f"(l1), "f"(l0));
    hi = h;
}

// ---------------------------------------------------------------------------
// TF32 NT GEMM v2: ldmatrix fragments + XOR-swizzled smem + 3-stage cp.async.
// C[m][n] = sum_k A[m*K+k] * W[n*K+k]
// 128x128 CTA tile, BK=32, 256 threads (8 warps, 2x4 grid, 64x32/warp).
// Stage layout: A tile 128 rows x 128B (8 x 16B chunks, chunk ^= row&7), B same.
// ---------------------------------------------------------------------------
constexpr int NSTG = 3;
constexpr int STGB = 32 * 1024;                 // A 16KB + B 16KB
constexpr int GEMM_SMEM = NSTG * STGB + 128;    // + alignment slack

__global__ void __launch_bounds__(256, 2) gemm_tf32(
    const float* __restrict__ A, const float* __restrict__ W,
    float* __restrict__ C, int Nr, int K)
{
    extern __shared__ char smraw[];
    const uint32_t smb = ((uint32_t)__cvta_generic_to_shared(smraw) + 127u) & ~127u;

    const int tid  = threadIdx.x;
    const int lane = tid & 31;
    const int warp = tid >> 5;
    const int wm   = warp & 1;
    const int wn   = warp >> 1;
    const int bm   = blockIdx.y * 128;
    const int bn   = blockIdx.x * 128;
    const int rr   = lane & 7;

    float acc[4][4][4];
#pragma unroll
    for (int i = 0; i < 4; i++)
#pragma unroll
        for (int j = 0; j < 4; j++)
#pragma unroll
            for (int r = 0; r < 4; r++) acc[i][j][r] = 0.f;

    // copy mapping: 4 (A,B) chunk pairs per thread per stage
    int cprow[4], cpch[4];
#pragma unroll
    for (int i = 0; i < 4; i++) {
        int idx = tid + i * 256;      // 0..1023
        cprow[i] = idx >> 3;
        cpch[i]  = idx & 7;
    }

    const int KT = K >> 5;

    auto load_stage = [&](int s, int kt) {
        const int k0 = kt << 5;
        const uint32_t sb = smb + s * STGB;
#pragma unroll
        for (int i = 0; i < 4; i++) {
            const int r = cprow[i], ch = cpch[i];
            const uint32_t dst = sb + r * 128 + ((ch ^ (r & 7)) << 4);
            cp_async16(dst,         A + (size_t)(bm + r) * K + k0 + ch * 4);
            cp_async16(dst + 16384, W + (size_t)(bn + r) * K + k0 + ch * 4);
        }
        asm volatile("cp.async.commit_group;\n");
    };

    load_stage(0, 0);
    load_stage(1, 1);

    // ldmatrix per-thread row/chunk components (chunk offset added per ks)
    // A blocks: blkid = lane>>3: row += (blkid&1)*8, chunk += blkid>>1
    const int a_blk_r = ((lane >> 3) & 1) << 3;
    const int a_blk_c = lane >> 4;
    // B blocks: row += (blkid>>1)*8, chunk += blkid&1
    const int b_blk_r = (lane >> 4) << 3;
    const int b_blk_c = (lane >> 3) & 1;

    for (int kt = 0; kt < KT; kt++) {
        if (kt == KT - 1) asm volatile("cp.async.wait_group 0;\n" ::: "memory");
        else              asm volatile("cp.async.wait_group 1;\n" ::: "memory");
        __syncthreads();

        if (kt + 2 < KT) load_stage((kt + 2) % NSTG, kt + 2);

        const uint32_t sbA = smb + (kt % NSTG) * STGB;
        const uint32_t sbB = sbA + 16384;

#pragma unroll
        for (int ks = 0; ks < 4; ks++) {
            const int c0 = ks << 1;
            uint32_t af[4][4], bf[4][2];
#pragma unroll
            for (int mt = 0; mt < 4; mt++) {
                const int row = wm * 64 + mt * 16 + a_blk_r + rr;
                const int ch  = c0 + a_blk_c;
                ldm_x4(af[mt][0], af[mt][1], af[mt][2], af[mt][3],
                       sbA + row * 128 + ((ch ^ (row & 7)) << 4));
            }
#pragma unroll
            for (int p = 0; p < 2; p++) {
                const int row = wn * 32 + p * 16 + b_blk_r + rr;
                const int ch  = c0 + b_blk_c;
                ldm_x4(bf[2 * p][0], bf[2 * p][1], bf[2 * p + 1][0], bf[2 * p + 1][1],
                       sbB + row * 128 + ((ch ^ (row & 7)) << 4));
            }
#pragma unroll
            for (int mt = 0; mt < 4; mt++)
#pragma unroll
                for (int j = 0; j < 4; j++)
                    af[mt][j] = f2tf32(__uint_as_float(af[mt][j]));
#pragma unroll
            for (int nt = 0; nt < 4; nt++) {
                bf[nt][0] = f2tf32(__uint_as_float(bf[nt][0]));
                bf[nt][1] = f2tf32(__uint_as_float(bf[nt][1]));
            }
#pragma unroll
            for (int mt = 0; mt < 4; mt++)
#pragma unroll
                for (int nt = 0; nt < 4; nt++)
                    mma_tf32(acc[mt][nt], af[mt], bf[nt]);
        }
    }

    // Store C
    const int g  = lane >> 2;
    const int tg = lane & 3;
#pragma unroll
    for (int mt = 0; mt < 4; mt++) {
#pragma unroll
        for (int nt = 0; nt < 4; nt++) {
            int row = bm + wm * 64 + mt * 16 + g;
            int col = bn + wn * 32 + nt * 8 + (tg << 1);
            *(float2*)(C + (size_t)row * Nr + col) =
                make_float2(acc[mt][nt][0], acc[mt][nt][1]);
            *(float2*)(C + (size_t)(row + 8) * Nr + col) =
                make_float2(acc[mt][nt][2], acc[mt][nt][3]);
        }
    }
}

// ---------------------------------------------------------------------------
// Fused RoPE + bf16-split pack + layout transform (unchanged from R4).
// ---------------------------------------------------------------------------
__global__ void ropepack(const float* __restrict__ q, const float* __restrict__ k,
                         const float* __restrict__ v,
                         const float* __restrict__ fc, const float* __restrict__ fs,
                         uint32_t* __restrict__ qp, uint32_t* __restrict__ kp,
                         uint32_t* __restrict__ vpt) {
    const int NQ = B * NH  * S * 64;
    const int NK = B * NKV * S * 64;
    int idx = blockIdx.x * blockDim.x + threadIdx.x;

    if (idx < NQ) {
        int d = idx & 63;
        int s = (idx >> 6) & (S - 1);
        int h = (idx >> 17) & 31;
        int b = idx >> 22;
        const float* src = q + ((size_t)(b * S + s) * NH + h) * HD + 2 * d;
        float xr = src[0], xi = src[1];
        float c = fc[s * 64 + d], sn = fs[s * 64 + d];
        float orr = xr * c - xi * sn;
        float oii = xr * sn + xi * c;
        *(uint2*)(qp + 2 * (size_t)idx) = make_uint2(packsplit(orr), packsplit(oii));
    } else if (idx < NQ + NK) {
        int i2 = idx - NQ;
        int d = i2 & 63;
        int s = (i2 >> 6) & (S - 1);
        int kvh = (i2 >> 17) & 7;
        int b = i2 >> 20;
        const float* src = k + ((size_t)(b * S + s) * NKV + kvh) * HD + 2 * d;
        float xr = src[0], xi = src[1];
        float c = fc[s * 64 + d], sn = fs[s * 64 + d];
        float orr = xr * c - xi * sn;
        float oii = xr * sn + xi * c;
        *(uint2*)(kp + 2 * (size_t)i2) = make_uint2(packsplit(orr), packsplit(oii));
    } else {
        int i3 = idx - NQ - NK;           // [b][kvh][d][s]
        int s = i3 & (S - 1);
        int d = (i3 >> 11) & 127;
        int kvh = (i3 >> 18) & 7;
        int b = i3 >> 21;
        float x = v[((size_t)(b * S + s) * NKV + kvh) * HD + d];
        vpt[i3] = packsplit(x);
    }
}

// ---------------------------------------------------------------------------
// Flash attention v2 with bf16x2-split mma.sync (unchanged from R4).
// ---------------------------------------------------------------------------
constexpr int QSTR = 136, KSTR = 136, VSTR = 72;
constexpr int SQ_OFF = 0;
constexpr int SK_OFF = 128 * QSTR;
constexpr int SV_OFF = SK_OFF + 2 * 64 * KSTR;
constexpr int ATTN_SMEM = (SV_OFF + 2 * 128 * VSTR) * 4;   // 212992 bytes

__global__ void __launch_bounds__(256, 1)
attn_mma(const uint32_t* __restrict__ qp, const uint32_t* __restrict__ kp,
         const uint32_t* __restrict__ vpt, float* __restrict__ O) {
    extern __shared__ uint32_t smw[];
    const uint32_t smb = (uint32_t)__cvta_generic_to_shared(smw);

    const int bh  = blockIdx.x;
    const int b   = bh >> 5;
    const int h   = bh & 31;
    const int kvh = h >> 2;
    const int qt  = blockIdx.y;
    const int qbase = qt * 128;
    const int tid = threadIdx.x;
    const int lane = tid & 31;
    const int w = tid >> 5;
    const int g = lane >> 2;
    const int tg = lane & 3;
    const float scale = 0.08838834764831845f;

    const uint32_t* qsrc = qp + ((size_t)(b * NH + h) * S + qbase) * HD;
    const uint32_t* ksrc = kp + (size_t)(b * NKV + kvh) * S * HD;
    const uint32_t* vsrc = vpt + (size_t)(b * NKV + kvh) * HD * S;

    for (int i = tid; i < 4096; i += 256) {
        int r = i >> 5, c = (i & 31) << 2;
        cp_async16(smb + (SQ_OFF + r * QSTR + c) * 4, qsrc + r * 128 + c);
    }
    {
        for (int i = tid; i < 2048; i += 256) {
            int r = i >> 5, c = (i & 31) << 2;
            cp_async16(smb + (SK_OFF + r * KSTR + c) * 4, ksrc + r * 128 + c);
        }
        for (int i = tid; i < 2048; i += 256) {
            int d = i >> 4, c = (i & 15) << 2;
            cp_async16(smb + (SV_OFF + d * VSTR + c) * 4, vsrc + (size_t)d * S + c);
        }
    }
    asm volatile("cp.async.commit_group;\n");

    float oacc[16][4];
#pragma unroll
    for (int nt = 0; nt < 16; nt++)
#pragma unroll
        for (int j = 0; j < 4; j++) oacc[nt][j] = 0.f;
    float mrun[2] = {-INFINITY, -INFINITY};
    float lrun[2] = {0.f, 0.f};

    const int nkv = 2 * qt + 2;
    const int rowbase = qbase + w * 16;

    for (int kt = 0; kt < nkv; kt++) {
        __syncthreads();
        if (kt + 1 < nkv) {
            const int st = (kt + 1) & 1;
            const uint32_t* ks = ksrc + (size_t)(kt + 1) * 64 * 128;
            for (int i = tid; i < 2048; i += 256) {
                int r = i >> 5, c = (i & 31) << 2;
                cp_async16(smb + (SK_OFF + st * 64 * KSTR + r * KSTR + c) * 4,
                           ks + r * 128 + c);
            }
            const uint32_t* vs = vsrc + (kt + 1) * 64;
            for (int i = tid; i < 2048; i += 256) {
                int d = i >> 4, c = (i & 15) << 2;
                cp_async16(smb + (SV_OFF + st * 128 * VSTR + d * VSTR + c) * 4,
                           vs + (size_t)d * S + c);
            }
        }
        asm volatile("cp.async.commit_group;\n");
        asm volatile("cp.async.wait_group 1;\n");
        __syncthreads();

        const bool active = (kt * 64 <= rowbase + 15);
        if (!active) continue;

        const uint32_t* K0 = smw + SK_OFF + (kt & 1) * 64 * KSTR;
        const uint32_t* V0 = smw + SV_OFF + (kt & 1) * 128 * VSTR;
        const uint32_t* Q0 = smw + SQ_OFF;

        float accS[8][4];
#pragma unroll
        for (int nt = 0; nt < 8; nt++)
#pragma unroll
            for (int j = 0; j < 4; j++) accS[nt][j] = 0.f;

#pragma unroll
        for (int s = 0; s < 8; s++) {
            const int d0 = 16 * s + 2 * tg;
            uint32_t ah[4], al[4];
            ldpair(Q0 + (w * 16 + g) * QSTR + d0,     ah[0], al[0]);
            ldpair(Q0 + (w * 16 + g + 8) * QSTR + d0, ah[1], al[1]);
            ldpair(Q0 + (w * 16 + g) * QSTR + d0 + 8, ah[2], al[2]);
            ldpair(Q0 + (w * 16 + g + 8) * QSTR + d0 + 8, ah[3], al[3]);
#pragma unroll
            for (int nt = 0; nt < 8; nt++) {
                uint32_t bh2[2], bl2[2];
                ldpair(K0 + (nt * 8 + g) * KSTR + d0,     bh2[0], bl2[0]);
                ldpair(K0 + (nt * 8 + g) * KSTR + d0 + 8, bh2[1], bl2[1]);
                mma_bf16(accS[nt], ah, bh2);
                mma_bf16(accS[nt], ah, bl2);
                mma_bf16(accS[nt], al, bh2);
            }
        }

        const bool needM = (kt * 64 + 63 > rowbase);
        float mt[2] = {-INFINITY, -INFINITY};
#pragma unroll
        for (int nt = 0; nt < 8; nt++) {
#pragma unroll
            for (int j = 0; j < 4; j++) {
                float sc = accS[nt][j] * scale;
                if (needM) {
                    int col = kt * 64 + nt * 8 + 2 * tg + (j & 1);
                    int row = rowbase + g + ((j >> 1) << 3);
                    if (col > row) sc = -1e30f;
                }
                accS[nt][j] = sc;
                mt[j >> 1] = fmaxf(mt[j >> 1], sc);
            }
        }
#pragma unroll
        for (int i = 0; i < 2; i++) {
            mt[i] = fmaxf(mt[i], __shfl_xor_sync(0xffffffffu, mt[i], 1));
            mt[i] = fmaxf(mt[i], __shfl_xor_sync(0xffffffffu, mt[i], 2));
        }
        float alpha[2], ls[2] = {0.f, 0.f};
#pragma unroll
        for (int i = 0; i < 2; i++) {
            float mnew = fmaxf(mrun[i], mt[i]);
            alpha[i] = __expf(mrun[i] - mnew);
            mrun[i] = mnew;
        }
#pragma unroll
        for (int nt = 0; nt < 8; nt++) {
#pragma unroll
            for (int j = 0; j < 4; j++) {
                float p = __expf(accS[nt][j] - mrun[j >> 1]);
                accS[nt][j] = p;
                ls[j >> 1] += p;
            }
        }
#pragma unroll
        for (int i = 0; i < 2; i++) {
            ls[i] += __shfl_xor_sync(0xffffffffu, ls[i], 1);
            ls[i] += __shfl_xor_sync(0xffffffffu, ls[i], 2);
            lrun[i] = lrun[i] * alpha[i] + ls[i];
        }
#pragma unroll
        for (int nt = 0; nt < 16; nt++) {
            oacc[nt][0] *= alpha[0]; oacc[nt][1] *= alpha[0];
            oacc[nt][2] *= alpha[1]; oacc[nt][3] *= alpha[1];
        }

#pragma unroll
        for (int s = 0; s < 4; s++) {
            uint32_t ph[4], pl[4];
            split2(accS[2 * s][0],     accS[2 * s][1],     ph[0], pl[0]);
            split2(accS[2 * s][2],     accS[2 * s][3],     ph[1], pl[1]);
            split2(accS[2 * s + 1][0], accS[2 * s + 1][1], ph[2], pl[2]);
            split2(accS[2 * s + 1][2], accS[2 * s + 1][3], ph[3], pl[3]);
            const int k0 = 16 * s + 2 * tg;
#pragma unroll
            for (int nt = 0; nt < 16; nt++) {
                uint32_t bh2[2], bl2[2];
                ldpair(V0 + (nt * 8 + g) * VSTR + k0,     bh2[0], bl2[0]);
                ldpair(V0 + (nt * 8 + g) * VSTR + k0 + 8, bh2[1], bl2[1]);
                mma_bf16(oacc[nt], ph, bh2);
                mma_bf16(oacc[nt], ph, bl2);
                mma_bf16(oacc[nt], pl, bh2);
            }
        }
    }

    const float i0 = 1.f / lrun[0];
    const float i1 = 1.f / lrun[1];
    const int row0 = rowbase + g;
    float* o0 = O + ((size_t)(b * S + row0) * NH + h) * HD;
    float* o1 = O + ((size_t)(b * S + row0 + 8) * NH + h) * HD;
#pragma unroll
    for (int nt = 0; nt < 16; nt++) {
        int col = nt * 8 + 2 * tg;
        *(float2*)(o0 + col) = make_float2(oacc[nt][0] * i0, oacc[nt][1] * i0);
        *(float2*)(o1 + col) = make_float2(oacc[nt][2] * i1, oacc[nt][3] * i1);
    }
}

// ---------------------------------------------------------------------------
// Launch
// ---------------------------------------------------------------------------
extern "C" void kernel_launch(void* const* d_in, const int* in_sizes, int n_in,
                              void* d_out, int out_size) {
    const float* x  = (const float*)d_in[0];
    const float* wq = (const float*)d_in[1];
    const float* wk = (const float*)d_in[2];
    const float* wv = (const float*)d_in[3];
    const float* wo = (const float*)d_in[4];
    const float* fc = (const float*)d_in[5];
    const float* fs = (const float*)d_in[6];
    float* out = (float*)d_out;

    float *q, *k, *v, *o;
    uint32_t *qpp, *kpp, *vptp;
    cudaGetSymbolAddress((void**)&q, g_q);
    cudaGetSymbolAddress((void**)&k, g_k);
    cudaGetSymbolAddress((void**)&v, g_v);
    cudaGetSymbolAddress((void**)&o, g_o);
    cudaGetSymbolAddress((void**)&qpp, g_qp);
    cudaGetSymbolAddress((void**)&kpp, g_kp);
    cudaGetSymbolAddress((void**)&vptp, g_vpt);

    cudaFuncSetAttribute(gemm_tf32, cudaFuncAttributeMaxDynamicSharedMemorySize, GEMM_SMEM);
    cudaFuncSetAttribute(attn_mma, cudaFuncAttributeMaxDynamicSharedMemorySize, ATTN_SMEM);

    // QKV projections (tf32 tensor cores, ldmatrix + 3-stage cp.async)
    gemm_tf32<<<dim3((NH  * HD) / 128, M / 128), 256, GEMM_SMEM>>>(x, wq, q, NH  * HD, DIM);
    gemm_tf32<<<dim3((NKV * HD) / 128, M / 128), 256, GEMM_SMEM>>>(x, wk, k, NKV * HD, DIM);
    gemm_tf32<<<dim3((NKV * HD) / 128, M / 128), 256, GEMM_SMEM>>>(x, wv, v, NKV * HD, DIM);

    // RoPE + split-pack + layout transform
    int total = B * NH * S * 64 + B * NKV * S * 64 + B * NKV * HD * S;
    ropepack<<<total / 256, 256>>>(q, k, v, fc, fs, qpp, kpp, vptp);

    // Tensor-core causal GQA flash attention
    attn_mma<<<dim3(B * NH, S / 128), 256, ATTN_SMEM>>>(qpp, kpp, vptp, o);

    // Output projection
    gemm_tf32<<<dim3(DIM / 128, M / 128), 256, GEMM_SMEM>>>(o, wo, out, DIM, DIM);
}